// round 13
// baseline (speedup 1.0000x reference)
#include <cuda_runtime.h>
#include <cuda_bf16.h>
#include <cstdint>

#define NQ 8
#define MQ 512
#define DQ 64
#define BQ 8192
#define BT 32
#define TILES 2
#define THREADS 256

constexpr int EMB_S = 72;    // bf16 element stride per emb row (conflict-free)
constexpr int LS_S  = 520;   // f32/u32 element stride for logits/samples rows

constexpr size_t OFF_KL     = (size_t)BQ * NQ * DQ;   // 4194304
constexpr size_t OFF_PPL    = OFF_KL + 1;
constexpr size_t OFF_LOGITS = OFF_KL + 2;

constexpr int SM_EH  = 0;
constexpr int SM_EL  = SM_EH  + MQ * EMB_S * 2;   // 73728
constexpr int SM_LS  = SM_EL  + MQ * EMB_S * 2;   // 147456 (66560 bytes)
constexpr int SM_XS  = SM_LS  + BT * LS_S * 4;    // 214016
constexpr int SM_XL  = SM_XS  + BT * EMB_S * 2;   // 218624
constexpr int SM_ESQ = SM_XL  + BT * EMB_S * 2;   // 223232
constexpr int SM_AVG = SM_ESQ + MQ * 4;           // 225280
constexpr int SM_RED = SM_AVG + MQ * 4;           // 227328
constexpr int SMEM_BYTES = SM_RED + 64;           // 227392

#define LOGM 6.2383246250395075f

// Zero-initialized at module load; vq_final resets them after reading, so
// every graph replay starts from zero (deterministic).
__device__ float g_avg[NQ * MQ];
__device__ float g_kl;

__device__ __forceinline__ float wredmax(float v) {
    #pragma unroll
    for (int o = 16; o; o >>= 1) v = fmaxf(v, __shfl_xor_sync(0xffffffffu, v, o));
    return v;
}
__device__ __forceinline__ float wredsum(float v) {
    #pragma unroll
    for (int o = 16; o; o >>= 1) v += __shfl_xor_sync(0xffffffffu, v, o);
    return v;
}

// Unbiased exp for f in ~[-0.7, 0]: degree-9 Taylor. KL is a huge
// cancellation; MUFU ex2/lg2 systematic bias would be amplified thousands of
// times into the KL relative error.
__device__ __forceinline__ float exp_taylor9(float f) {
    float p = 2.75573192e-6f;
    p = fmaf(p, f, 2.48015873e-5f);
    p = fmaf(p, f, 1.98412698e-4f);
    p = fmaf(p, f, 1.38888889e-3f);
    p = fmaf(p, f, 8.33333333e-3f);
    p = fmaf(p, f, 4.16666667e-2f);
    p = fmaf(p, f, 1.66666667e-1f);
    p = fmaf(p, f, 0.5f);
    p = fmaf(p, f, 1.0f);
    p = fmaf(p, f, 1.0f);
    return p;
}

// Pack two floats into bf16x2 hi-word + produce the bf16x2 residual word.
__device__ __forceinline__ uint32_t pack2_hilo(float a, float b, uint32_t& lopk) {
    __nv_bfloat16 ha = __float2bfloat16(a), hb = __float2bfloat16(b);
    float la = a - __bfloat162float(ha);
    float lb = b - __bfloat162float(hb);
    lopk = (uint32_t)__bfloat16_as_ushort(__float2bfloat16(la)) |
           ((uint32_t)__bfloat16_as_ushort(__float2bfloat16(lb)) << 16);
    return (uint32_t)__bfloat16_as_ushort(ha) |
           ((uint32_t)__bfloat16_as_ushort(hb) << 16);
}

__device__ __forceinline__ void mma16816(float* c, const uint32_t* a, const uint32_t* b) {
    asm volatile(
        "mma.sync.aligned.m16n8k16.row.col.f32.bf16.bf16.f32 "
        "{%0,%1,%2,%3}, {%4,%5,%6,%7}, {%8,%9}, {%0,%1,%2,%3};\n"
        : "+f"(c[0]), "+f"(c[1]), "+f"(c[2]), "+f"(c[3])
        : "r"(a[0]), "r"(a[1]), "r"(a[2]), "r"(a[3]), "r"(b[0]), "r"(b[1]));
}

// ---------------------------------------------------------------------------
// One CTA = (n, TILES consecutive 32-row b-tiles). emb staged ONCE per CTA
// (e_sq computed during staging via 16-lane shuffle reductions). Per tile:
//   Phase 1: logits via split-bf16 mma
//   Phase 2: softmax/KL/ret_logits + gumbel softmax -> packed hi|lo samples
//   Phase 3: quantized via scalar-LDS split-bf16 mma
// ---------------------------------------------------------------------------
__global__ void __launch_bounds__(THREADS, 1)
vq_main(const float* __restrict__ x, const float* __restrict__ emb,
        const float* __restrict__ u, const float* __restrict__ tau,
        float* __restrict__ out) {
    extern __shared__ char smem[];
    __nv_bfloat16* EH  = (__nv_bfloat16*)(smem + SM_EH);
    __nv_bfloat16* EL  = (__nv_bfloat16*)(smem + SM_EL);
    float*         LS  = (float*)(smem + SM_LS);
    __nv_bfloat16* XS  = (__nv_bfloat16*)(smem + SM_XS);
    __nv_bfloat16* XL  = (__nv_bfloat16*)(smem + SM_XL);
    float*         ESQ = (float*)(smem + SM_ESQ);
    float*         AVG = (float*)(smem + SM_AVG);
    float*         RED = (float*)(smem + SM_RED);

    const int n   = blockIdx.y;
    const int tid = threadIdx.x;
    const int lane = tid & 31;
    const int w    = tid >> 5;
    const int g    = lane >> 2;
    const int tg   = lane & 3;
    const float invtau = 1.0f / tau[0];

    // ---- stage emb hi/lo ONCE; e_sq via 16-lane shuffle reduction.
    // i = tid*4 + iter*1024: the 16 consecutive lanes tid>>4 cover exactly
    // one 64-elem emb row, so xor-shuffles 1,2,4,8 reduce its square-sum. ----
    const float* embn = emb + (size_t)n * MQ * DQ;
    for (int i = tid * 4; i < MQ * DQ; i += THREADS * 4) {
        const float4 v4 = *(const float4*)&embn[i];
        const int m = i >> 6, d = i & 63;
        uint32_t lo01, lo23;
        const uint32_t h01 = pack2_hilo(v4.x, v4.y, lo01);
        const uint32_t h23 = pack2_hilo(v4.z, v4.w, lo23);
        *(uint2*)&EH[m * EMB_S + d] = make_uint2(h01, h23);
        *(uint2*)&EL[m * EMB_S + d] = make_uint2(lo01, lo23);
        float p = fmaf(v4.x, v4.x, v4.y * v4.y) + fmaf(v4.z, v4.z, v4.w * v4.w);
        #pragma unroll
        for (int o = 1; o < 16; o <<= 1) p += __shfl_xor_sync(0xffffffffu, p, o);
        if ((lane & 15) == 0) ESQ[m] = p;
    }
    for (int i = tid; i < MQ; i += THREADS) AVG[i] = 0.f;

    const int rt  = w & 1;           // row tile (phases 1&3)
    const int cb  = w >> 1;          // phase-1 col block
    const int dt0 = (w >> 1) * 2;    // phase-3 d tiles

    float kl_acc = 0.f;

    for (int t = 0; t < TILES; t++) {
        const int b0 = (blockIdx.x * TILES + t) * BT;

        // ---- stage x tile hi/lo (float4 loads) ----
        for (int i = tid * 4; i < BT * DQ; i += THREADS * 4) {
            const int r = i >> 6, d = i & 63;
            const float4 v4 = *(const float4*)&x[(size_t)(b0 + r) * (NQ * DQ) + n * DQ + d];
            uint32_t lo01, lo23;
            const uint32_t h01 = pack2_hilo(v4.x, v4.y, lo01);
            const uint32_t h23 = pack2_hilo(v4.z, v4.w, lo23);
            *(uint2*)&XS[r * EMB_S + d] = make_uint2(h01, h23);
            *(uint2*)&XL[r * EMB_S + d] = make_uint2(lo01, lo23);
        }
        __syncthreads();

        // ---- Phase 1: GEMM1 (32 x 512, K=64), split-bf16 mma ----
        {
            const int r0 = rt * 16;
            uint32_t ah[4][4], al[4][4];
            #pragma unroll
            for (int ks = 0; ks < 4; ks++) {
                const int kb = ks * 16 + tg * 2;
                ah[ks][0] = *(const uint32_t*)&XS[(r0 + g) * EMB_S + kb];
                ah[ks][1] = *(const uint32_t*)&XS[(r0 + g + 8) * EMB_S + kb];
                ah[ks][2] = *(const uint32_t*)&XS[(r0 + g) * EMB_S + kb + 8];
                ah[ks][3] = *(const uint32_t*)&XS[(r0 + g + 8) * EMB_S + kb + 8];
                al[ks][0] = *(const uint32_t*)&XL[(r0 + g) * EMB_S + kb];
                al[ks][1] = *(const uint32_t*)&XL[(r0 + g + 8) * EMB_S + kb];
                al[ks][2] = *(const uint32_t*)&XL[(r0 + g) * EMB_S + kb + 8];
                al[ks][3] = *(const uint32_t*)&XL[(r0 + g + 8) * EMB_S + kb + 8];
            }
            #pragma unroll
            for (int tt = 0; tt < 16; tt++) {
                const int n0 = cb * 128 + tt * 8;
                float c[4] = {0.f, 0.f, 0.f, 0.f};
                #pragma unroll
                for (int ks = 0; ks < 4; ks++) {
                    const int kb = ks * 16 + tg * 2;
                    uint32_t bh[2], bl[2];
                    bh[0] = *(const uint32_t*)&EH[(n0 + g) * EMB_S + kb];
                    bh[1] = *(const uint32_t*)&EH[(n0 + g) * EMB_S + kb + 8];
                    bl[0] = *(const uint32_t*)&EL[(n0 + g) * EMB_S + kb];
                    bl[1] = *(const uint32_t*)&EL[(n0 + g) * EMB_S + kb + 8];
                    mma16816(c, ah[ks], bh);
                    mma16816(c, ah[ks], bl);
                    mma16816(c, al[ks], bh);
                }
                const int col = n0 + tg * 2;
                LS[(r0 + g) * LS_S + col]         = 2.f * c[0] - ESQ[col];
                LS[(r0 + g) * LS_S + col + 1]     = 2.f * c[1] - ESQ[col + 1];
                LS[(r0 + g + 8) * LS_S + col]     = 2.f * c[2] - ESQ[col];
                LS[(r0 + g + 8) * LS_S + col + 1] = 2.f * c[3] - ESQ[col + 1];
            }
        }
        __syncthreads();

        // ---- Phase 2: softmax, ret_logits, KL, gumbel softmax, samples ----
        {
            float rowacc[16];
            #pragma unroll
            for (int i = 0; i < 16; i++) rowacc[i] = 0.f;

            const float* urow0 = u + ((size_t)n * BQ + b0 + w * 4) * MQ;
            float ur[16];
            #pragma unroll
            for (int i = 0; i < 16; i++) ur[i] = __ldcs(&urow0[lane + i * 32]);

            for (int rr = 0; rr < 4; rr++) {
                const int r = w * 4 + rr;
                const size_t brow = (size_t)b0 + r;

                float gmb[16];
                #pragma unroll
                for (int i = 0; i < 16; i++) gmb[i] = -__logf(-__logf(ur[i]));

                if (rr < 3) {
                    const float* unext = urow0 + (size_t)(rr + 1) * MQ;
                    #pragma unroll
                    for (int i = 0; i < 16; i++) ur[i] = __ldcs(&unext[lane + i * 32]);
                }

                float l[16];
                #pragma unroll
                for (int i = 0; i < 16; i++) l[i] = LS[r * LS_S + lane + i * 32];

                float t2[16];
                #pragma unroll
                for (int i = 0; i < 16; i++) t2[i] = (l[i] + gmb[i]) * invtau;

                float mx = l[0];
                #pragma unroll
                for (int i = 1; i < 16; i++) mx = fmaxf(mx, l[i]);
                mx = wredmax(mx);

                float mx2 = t2[0];
                #pragma unroll
                for (int i = 1; i < 16; i++) mx2 = fmaxf(mx2, t2[i]);
                mx2 = wredmax(mx2);

                float s1l = 0.f, stfl = 0.f;
                #pragma unroll
                for (int i = 0; i < 16; i++) {
                    const float f = l[i] - mx;
                    const float tv = exp_taylor9(f);
                    s1l += tv;
                    stfl = fmaf(tv, f, stfl);
                }

                float s2l = 0.f;
                #pragma unroll
                for (int i = 0; i < 16; i++) { t2[i] = __expf(t2[i] - mx2); s2l += t2[i]; }

                const float s1  = wredsum(s1l);
                const float stf = wredsum(stfl);
                const float inv2 = 1.0f / wredsum(s2l);

                const float lg1p = log1pf(fmaf(s1, 1.0f / 512.0f, -1.0f));
                const float logZ = mx + LOGM + lg1p;
                kl_acc += stf / s1 - lg1p;   // KL_row (identical across lanes)

                float* outlp = out + OFF_LOGITS + (brow * NQ + n) * MQ;
                #pragma unroll
                for (int i = 0; i < 16; i++) {
                    __stcs(&outlp[lane + i * 32], l[i] - logZ);
                }

                uint32_t* SSM = (uint32_t*)LS;
                #pragma unroll
                for (int i = 0; i < 16; i++) {
                    const float s = t2[i] * inv2;
                    rowacc[i] += s;
                    __nv_bfloat16 h = __float2bfloat16(s);
                    float lo = s - __bfloat162float(h);
                    __nv_bfloat16 hl = __float2bfloat16(lo);
                    uint32_t pk = (uint32_t)__bfloat16_as_ushort(h) |
                                  ((uint32_t)__bfloat16_as_ushort(hl) << 16);
                    SSM[r * LS_S + lane + i * 32] = pk;
                }
            }
            #pragma unroll
            for (int i = 0; i < 16; i++) atomicAdd(&AVG[lane + i * 32], rowacc[i]);
        }
        __syncthreads();

        // ---- Phase 3: GEMM2 quantized = samples @ emb (scalar-LDS path) ----
        {
            const uint32_t* SSM = (const uint32_t*)LS;
            const uint16_t* EH16 = (const uint16_t*)EH;
            const uint16_t* EL16 = (const uint16_t*)EL;
            const int ra  = rt * 16 + g;
            float c0[4] = {0.f, 0.f, 0.f, 0.f};
            float c1[4] = {0.f, 0.f, 0.f, 0.f};

            #pragma unroll 4
            for (int ks = 0; ks < 32; ks++) {
                const int kb = ks * 16 + tg * 2;
                uint32_t ah[4], al[4];
                #pragma unroll
                for (int j = 0; j < 4; j++) {
                    const int row = ra + (j & 1) * 8;
                    const int kk  = kb + (j >> 1) * 8;
                    const uint32_t p0 = SSM[row * LS_S + kk];
                    const uint32_t p1 = SSM[row * LS_S + kk + 1];
                    ah[j] = __byte_perm(p0, p1, 0x5410);   // hi halves
                    al[j] = __byte_perm(p0, p1, 0x7632);   // lo halves
                }
                #pragma unroll
                for (int dt = 0; dt < 2; dt++) {
                    const int dcol = (dt0 + dt) * 8 + g;
                    uint32_t bh[2], bl[2];
                    bh[0] = (uint32_t)EH16[kb * EMB_S + dcol]       | ((uint32_t)EH16[(kb + 1) * EMB_S + dcol] << 16);
                    bh[1] = (uint32_t)EH16[(kb + 8) * EMB_S + dcol] | ((uint32_t)EH16[(kb + 9) * EMB_S + dcol] << 16);
                    bl[0] = (uint32_t)EL16[kb * EMB_S + dcol]       | ((uint32_t)EL16[(kb + 1) * EMB_S + dcol] << 16);
                    bl[1] = (uint32_t)EL16[(kb + 8) * EMB_S + dcol] | ((uint32_t)EL16[(kb + 9) * EMB_S + dcol] << 16);
                    float* cc = dt ? c1 : c0;
                    mma16816(cc, ah, bh);
                    mma16816(cc, ah, bl);
                    mma16816(cc, al, bh);
                }
            }
            #pragma unroll
            for (int dt = 0; dt < 2; dt++) {
                const float* cc = dt ? c1 : c0;
                const int dcol = (dt0 + dt) * 8 + tg * 2;
                const size_t base0 = ((size_t)(b0 + ra) * NQ + n) * DQ + dcol;
                const size_t base1 = ((size_t)(b0 + ra + 8) * NQ + n) * DQ + dcol;
                __stcs(&out[base0],     cc[0]);
                __stcs(&out[base0 + 1], cc[1]);
                __stcs(&out[base1],     cc[2]);
                __stcs(&out[base1 + 1], cc[3]);
            }
        }
        __syncthreads();
    }

    // ---- flush KL + avg_probs ----
    if (lane == 0) RED[w] = kl_acc;
    __syncthreads();
    if (tid == 0) {
        float s = 0.f;
        #pragma unroll
        for (int i = 0; i < 8; i++) s += RED[i];
        atomicAdd(&g_kl, s);
    }
    for (int i = tid; i < MQ; i += THREADS) atomicAdd(&g_avg[n * MQ + i], AVG[i]);
}

// ---------------------------------------------------------------------------
// Finalize: KL mean, perplexity sum. Then RESET the global accumulators so
// the next graph replay starts from zero (deterministic).
// ---------------------------------------------------------------------------
__global__ void vq_final(float* __restrict__ out) {
    const int tid = threadIdx.x;
    const int w = tid >> 5, lane = tid & 31;
    __shared__ float red[8];
    if (w < 8) {
        float acc = 0.f;
        #pragma unroll
        for (int i = 0; i < 16; i++) {
            float a = g_avg[w * MQ + lane + i * 32] * (1.0f / (float)BQ);
            acc = fmaf(a, __logf(a + 1e-10f), acc);
        }
        acc = wredsum(acc);
        if (lane == 0) red[w] = acc;
    }
    __syncthreads();   // all g_avg reads complete before the reset below
    if (tid == 0) {
        float s = 0.f;
        #pragma unroll
        for (int i = 0; i < 8; i++) s += __expf(-red[i]);
        out[OFF_PPL] = s;
        out[OFF_KL]  = g_kl * (1.0f / (float)BQ);
        g_kl = 0.f;
    }
    for (int i = tid; i < NQ * MQ; i += 256) g_avg[i] = 0.f;
}

extern "C" void kernel_launch(void* const* d_in, const int* in_sizes, int n_in,
                              void* d_out, int out_size) {
    const float* x   = (const float*)d_in[0];
    const float* emb = (const float*)d_in[1];
    const float* u   = (const float*)d_in[2];
    const float* tau = (const float*)d_in[3];
    float* out = (float*)d_out;

    cudaFuncSetAttribute(vq_main, cudaFuncAttributeMaxDynamicSharedMemorySize, SMEM_BYTES);

    vq_main<<<dim3(BQ / (BT * TILES), NQ, 1), THREADS, SMEM_BYTES>>>(x, emb, u, tau, out);
    vq_final<<<1, 256>>>(out);
}